// round 8
// baseline (speedup 1.0000x reference)
#include <cuda_runtime.h>
#include <cuda_bf16.h>
#include <cstdint>

// ---------------- Problem constants ----------------
#define BATCH   2048
#define NCOLS   32
#define CATD    2000
#define HID     128
#define VTOT    64000

// ---------------- Device scratch (no allocs allowed) ----------------
__device__ __align__(16) __nv_bfloat16 g_Wb[VTOT * HID];      // 16 MB  bf16 W_dec
__device__ __align__(16) float         g_c[VTOT];             // 256 KB c[v]
__device__ __align__(16) __nv_bfloat16 g_delta[BATCH * HID];  // 512 KB bf16 (y - ybar)
__device__ __align__(16) __nv_bfloat16 g_WTb[VTOT * HID];     // 16 MB  W_enc^T [v][h] bf16

__device__ __forceinline__ uint32_t smem_to_u32(const void* p) {
    uint32_t a;
    asm("{ .reg .u64 t; cvta.to.shared.u64 t, %1; cvt.u32.u64 %0, t; }" : "=r"(a) : "l"(p));
    return a;
}

#define CP_ASYNC_CG16(dst_smem, src_gmem) \
    asm volatile("cp.async.cg.shared.global [%0], [%1], 16;" \
        :: "r"(dst_smem), "l"(src_gmem) : "memory")
#define CP_ASYNC_COMMIT() asm volatile("cp.async.commit_group;" ::: "memory")
#define CP_ASYNC_WAIT(n)  asm volatile("cp.async.wait_group %0;" :: "n"(n) : "memory")

__device__ __forceinline__ void stg_cs_v4(float* p, float x, float y, float z, float w) {
    asm volatile("st.global.cs.v4.f32 [%0], {%1,%2,%3,%4};"
                 :: "l"(p), "f"(x), "f"(y), "f"(z), "f"(w) : "memory");
}

// ---------------- Kernel 0a: transpose W_enc [HID,VTOT] -> g_WTb [VTOT,HID] (bf16) -----------
__global__ void __launch_bounds__(256) transpose_kernel(const float* __restrict__ Wenc) {
    extern __shared__ float st[];              // [128 v][129]
    int v0 = blockIdx.x * 128;
    int t  = threadIdx.x;
    #pragma unroll
    for (int it = 0; it < 64; ++it) {
        int idx = it * 256 + t;
        int v = idx & 127;
        int h = idx >> 7;
        st[v * 129 + h] = Wenc[(size_t)h * VTOT + v0 + v];
    }
    __syncthreads();
    #pragma unroll
    for (int it = 0; it < 16; ++it) {
        int idx = it * 256 + t;
        int h4 = (idx & 31) * 4;
        int v  = idx >> 5;
        __nv_bfloat162 p0 = __floats2bfloat162_rn(st[v * 129 + h4 + 0], st[v * 129 + h4 + 1]);
        __nv_bfloat162 p1 = __floats2bfloat162_rn(st[v * 129 + h4 + 2], st[v * 129 + h4 + 3]);
        uint2 pk;
        pk.x = *reinterpret_cast<uint32_t*>(&p0);
        pk.y = *reinterpret_cast<uint32_t*>(&p1);
        *reinterpret_cast<uint2*>(g_WTb + (size_t)(v0 + v) * HID + h4) = pk;
    }
}

// ---------------- Kernel 0b: prep — W_dec -> bf16, c[v] ----------------
__global__ void __launch_bounds__(256) prep_kernel(const float* __restrict__ Wdec,
                                                   const float* __restrict__ benc,
                                                   const float* __restrict__ bdec) {
    int gw   = (blockIdx.x * 256 + threadIdx.x) >> 5;
    int lane = threadIdx.x & 31;
    if (gw >= VTOT) return;

    float4 w = *reinterpret_cast<const float4*>(Wdec + (size_t)gw * HID + lane * 4);

    float b0 = benc[lane * 4 + 0], b1 = benc[lane * 4 + 1];
    float b2 = benc[lane * 4 + 2], b3 = benc[lane * 4 + 3];
    float dot = w.x / (1.0f + __expf(-b0)) + w.y / (1.0f + __expf(-b1))
              + w.z / (1.0f + __expf(-b2)) + w.w / (1.0f + __expf(-b3));

    __nv_bfloat162 p0 = __floats2bfloat162_rn(w.x, w.y);
    __nv_bfloat162 p1 = __floats2bfloat162_rn(w.z, w.w);
    uint2 pk;
    pk.x = *reinterpret_cast<uint32_t*>(&p0);
    pk.y = *reinterpret_cast<uint32_t*>(&p1);
    *reinterpret_cast<uint2*>(g_Wb + (size_t)gw * HID + lane * 4) = pk;

    #pragma unroll
    for (int o = 16; o > 0; o >>= 1) dot += __shfl_xor_sync(0xffffffffu, dot, o);
    if (lane == 0) g_c[gw] = dot + bdec[gw];
}

// ---------------- Kernel 2: encode (bf16 gather rows, fp32 accumulate) ----------------
__global__ void __launch_bounds__(256) encode_kernel(const int* __restrict__ xcat,
                                                     const float* __restrict__ benc,
                                                     float* __restrict__ yout) {
    int wid  = threadIdx.x >> 5;
    int lane = threadIdx.x & 31;
    int b    = blockIdx.x * 8 + wid;

    int gidx = xcat[b * NCOLS + lane] + lane * CATD;

    float a0 = 0.f, a1 = 0.f, a2 = 0.f, a3 = 0.f;
    #pragma unroll
    for (int i = 0; i < NCOLS; ++i) {
        int gi = __shfl_sync(0xffffffffu, gidx, i);
        uint2 pk = *reinterpret_cast<const uint2*>(g_WTb + (size_t)gi * HID + lane * 4);
        __nv_bfloat162 p0 = *reinterpret_cast<__nv_bfloat162*>(&pk.x);
        __nv_bfloat162 p1 = *reinterpret_cast<__nv_bfloat162*>(&pk.y);
        a0 += __bfloat162float(p0.x); a1 += __bfloat162float(p0.y);
        a2 += __bfloat162float(p1.x); a3 += __bfloat162float(p1.y);
    }

    float4 be = *reinterpret_cast<const float4*>(benc + lane * 4);
    float y0 = 1.0f / (1.0f + __expf(-(a0 + be.x)));
    float y1 = 1.0f / (1.0f + __expf(-(a1 + be.y)));
    float y2 = 1.0f / (1.0f + __expf(-(a2 + be.z)));
    float y3 = 1.0f / (1.0f + __expf(-(a3 + be.w)));
    if (yout) {
        float4 yv = {y0, y1, y2, y3};
        *reinterpret_cast<float4*>(yout + (size_t)b * HID + lane * 4) = yv;
    }
    float d0 = y0 - 1.0f / (1.0f + __expf(-be.x));
    float d1 = y1 - 1.0f / (1.0f + __expf(-be.y));
    float d2 = y2 - 1.0f / (1.0f + __expf(-be.z));
    float d3 = y3 - 1.0f / (1.0f + __expf(-be.w));
    __nv_bfloat162 p0 = __floats2bfloat162_rn(d0, d1);
    __nv_bfloat162 p1 = __floats2bfloat162_rn(d2, d3);
    uint2 pk;
    pk.x = *reinterpret_cast<uint32_t*>(&p0);
    pk.y = *reinterpret_cast<uint32_t*>(&p1);
    *reinterpret_cast<uint2*>(g_delta + (size_t)b * HID + lane * 4) = pk;
}

// ---------------- Kernel 3: decode GEMM — 512 threads, 16 warps 4(M)x4(N), warp tile 32x32 ----
// Persistent over N (grid 16 x NGRP), A tile loaded once to smem, B double-buffered cp.async.
// B rows permuted within 16-row groups for STG.128 epilogue (validated R5/R6 mapping).

#define TILE_M 128
#define TILE_N 128
#define NGRP   18
#define NBLKS  (VTOT / TILE_N)           // 500
#define SROWB  272
#define TILE_BYTES (128 * SROWB)         // 34816
#define SM_A_OFF 0
#define SM_B_OFF TILE_BYTES
#define SM_TOTAL (3 * TILE_BYTES)        // 104448 (A + 2x B)

__device__ __forceinline__ void ldmatrix_x4(uint32_t (&r)[4], uint32_t addr) {
    asm volatile("ldmatrix.sync.aligned.m8n8.x4.shared.b16 {%0,%1,%2,%3}, [%4];"
                 : "=r"(r[0]), "=r"(r[1]), "=r"(r[2]), "=r"(r[3]) : "r"(addr));
}
__device__ __forceinline__ void mma_bf16(float (&d)[4], const uint32_t (&a)[4], const uint32_t* b) {
    asm volatile(
        "mma.sync.aligned.m16n8k16.row.col.f32.bf16.bf16.f32 "
        "{%0,%1,%2,%3}, {%4,%5,%6,%7}, {%8,%9}, {%0,%1,%2,%3};"
        : "+f"(d[0]), "+f"(d[1]), "+f"(d[2]), "+f"(d[3])
        : "r"(a[0]), "r"(a[1]), "r"(a[2]), "r"(a[3]), "r"(b[0]), "r"(b[1]));
}

__device__ __forceinline__ void load_B_tile(uint32_t sdst, const char* src, int tid) {
    #pragma unroll
    for (int it = 0; it < 4; ++it) {
        int idx = it * 512 + tid;                 // 0..2047 chunks of 16B
        int row = idx >> 4;
        int ch  = (idx & 15) * 16;
        int gg  = row & 15;
        int q   = gg >> 2, r = gg & 3;
        int slot = (r < 2) ? (q * 2 + r) : (8 + q * 2 + (r & 1));
        int prow = (row & ~15) | slot;
        CP_ASYNC_CG16(sdst + prow * SROWB + ch, src + row * 256 + ch);
    }
}

__global__ void __launch_bounds__(512, 2) decode_gemm(float* __restrict__ zout) {
    extern __shared__ char smem[];
    uint32_t sbase = smem_to_u32(smem);
    int tid  = threadIdx.x;
    int wid  = tid >> 5;
    int lane = tid & 31;
    int mblk = blockIdx.x;   // 0..15
    int ygrp = blockIdx.y;   // 0..NGRP-1

    // ---- A tile once ----
    const char* Asrc = reinterpret_cast<const char*>(g_delta + (size_t)mblk * TILE_M * HID);
    #pragma unroll
    for (int it = 0; it < 4; ++it) {
        int idx = it * 512 + tid;
        int row = idx >> 4;
        int ch  = (idx & 15) * 16;
        CP_ASYNC_CG16(sbase + SM_A_OFF + row * SROWB + ch, Asrc + row * 256 + ch);
    }
    int nb = ygrp;
    load_B_tile(sbase + SM_B_OFF, reinterpret_cast<const char*>(g_Wb + (size_t)nb * TILE_N * HID), tid);
    CP_ASYNC_COMMIT();

    int wm = wid & 3;        // M group: 32 rows
    int wn = wid >> 2;       // N group: 32 cols
    int j  = lane & 3;
    int colLoc = wn * 32 + j * 4;

    uint32_t aBase = sbase + SM_A_OFF + (uint32_t)(wm * 32 + (lane & 15)) * SROWB + ((lane >> 4) << 4);
    uint32_t bOff  = (uint32_t)(wn * 32 + ((lane >> 4) << 3) + (lane & 7)) * SROWB
                   + (((lane >> 3) & 1) << 4);
    int rowBase = mblk * TILE_M + wm * 32 + (lane >> 2);

    CP_ASYNC_WAIT(0);
    __syncthreads();

    int buf = 0;
    while (true) {
        int nbn = nb + NGRP;
        bool more = (nbn < NBLKS);
        if (more) {
            load_B_tile(sbase + SM_B_OFF + (buf ^ 1) * TILE_BYTES,
                        reinterpret_cast<const char*>(g_Wb + (size_t)nbn * TILE_N * HID), tid);
            CP_ASYNC_COMMIT();
        }

        const float* ctab = g_c + (size_t)nb * TILE_N;
        float4 cv0 = *reinterpret_cast<const float4*>(ctab + colLoc);
        float4 cv1 = *reinterpret_cast<const float4*>(ctab + colLoc + 16);

        float acc[2][4][4];
        #pragma unroll
        for (int i = 0; i < 2; ++i)
            #pragma unroll
            for (int jj = 0; jj < 4; ++jj)
                #pragma unroll
                for (int k = 0; k < 4; ++k) acc[i][jj][k] = 0.0f;

        uint32_t bBase = sbase + SM_B_OFF + (uint32_t)buf * TILE_BYTES + bOff;
        #pragma unroll
        for (int ks = 0; ks < 8; ++ks) {
            uint32_t koff = (uint32_t)ks * 32u;
            uint32_t a[2][4];
            uint32_t b[2][4];
            #pragma unroll
            for (int mf = 0; mf < 2; ++mf)
                ldmatrix_x4(a[mf], aBase + (uint32_t)mf * 16u * SROWB + koff);
            #pragma unroll
            for (int p = 0; p < 2; ++p)
                ldmatrix_x4(b[p], bBase + (uint32_t)p * 16u * SROWB + koff);
            #pragma unroll
            for (int mf = 0; mf < 2; ++mf)
                #pragma unroll
                for (int nf = 0; nf < 4; ++nf)
                    mma_bf16(acc[mf][nf], a[mf], &b[nf >> 1][(nf & 1) * 2]);
        }

        // ---- STG.128 streaming epilogue ----
        size_t colG = (size_t)nb * TILE_N + colLoc;
        #pragma unroll
        for (int mf = 0; mf < 2; ++mf) {
            float* z0 = zout + (size_t)(rowBase + mf * 16) * VTOT + colG;
            float* z1 = z0 + 8 * VTOT;
            stg_cs_v4(z0,      acc[mf][0][0] + cv0.x, acc[mf][0][1] + cv0.y,
                               acc[mf][1][0] + cv0.z, acc[mf][1][1] + cv0.w);
            stg_cs_v4(z1,      acc[mf][0][2] + cv0.x, acc[mf][0][3] + cv0.y,
                               acc[mf][1][2] + cv0.z, acc[mf][1][3] + cv0.w);
            stg_cs_v4(z0 + 16, acc[mf][2][0] + cv1.x, acc[mf][2][1] + cv1.y,
                               acc[mf][3][0] + cv1.z, acc[mf][3][1] + cv1.w);
            stg_cs_v4(z1 + 16, acc[mf][2][2] + cv1.x, acc[mf][2][3] + cv1.y,
                               acc[mf][3][2] + cv1.z, acc[mf][3][3] + cv1.w);
        }

        if (!more) break;
        CP_ASYNC_WAIT(0);
        __syncthreads();
        buf ^= 1;
        nb = nbn;
    }
}

// ---------------- Launch ----------------
extern "C" void kernel_launch(void* const* d_in, const int* in_sizes, int n_in,
                              void* d_out, int out_size) {
    const int*   xcat = (const int*)d_in[0];
    const float* Wenc = (const float*)d_in[1];
    const float* benc = (const float*)d_in[2];
    const float* Wdec = (const float*)d_in[3];
    const float* bdec = (const float*)d_in[4];

    float* out = (float*)d_out;
    long long ztotal = (long long)BATCH * VTOT;
    long long zoff   = (long long)out_size - ztotal;
    if (zoff < 0) zoff = 0;
    float* zout = out + zoff;
    float* yout = (zoff >= (long long)BATCH * HID) ? out : nullptr;

    cudaFuncSetAttribute(decode_gemm, cudaFuncAttributeMaxDynamicSharedMemorySize, SM_TOTAL);
    cudaFuncSetAttribute(transpose_kernel, cudaFuncAttributeMaxDynamicSharedMemorySize, 128 * 129 * 4);

    transpose_kernel<<<VTOT / 128, 256, 128 * 129 * 4>>>(Wenc);
    prep_kernel<<<VTOT / 8, 256>>>(Wdec, benc, bdec);
    encode_kernel<<<BATCH / 8, 256>>>(xcat, benc, yout);
    decode_gemm<<<dim3(BATCH / TILE_M, NGRP), 512, SM_TOTAL>>>(zout);
}

// round 9
// speedup vs baseline: 1.3540x; 1.3540x over previous
#include <cuda_runtime.h>
#include <cuda_bf16.h>
#include <cstdint>

// ---------------- Problem constants ----------------
#define BATCH   2048
#define NCOLS   32
#define CATD    2000
#define HID     128
#define VTOT    64000

// ---------------- Device scratch (no allocs allowed) ----------------
__device__ __align__(16) __nv_bfloat16 g_Wb[VTOT * HID];      // 16 MB  bf16 W_dec
__device__ __align__(16) float         g_c[VTOT];             // 256 KB c[v]
__device__ __align__(16) __nv_bfloat16 g_delta[BATCH * HID];  // 512 KB bf16 (y - ybar)
__device__ __align__(16) __nv_bfloat16 g_WTb[VTOT * HID];     // 16 MB  W_enc^T [v][h] bf16

__device__ __forceinline__ uint32_t smem_to_u32(const void* p) {
    uint32_t a;
    asm("{ .reg .u64 t; cvta.to.shared.u64 t, %1; cvt.u32.u64 %0, t; }" : "=r"(a) : "l"(p));
    return a;
}

#define CP_ASYNC_CG16(dst_smem, src_gmem) \
    asm volatile("cp.async.cg.shared.global [%0], [%1], 16;" \
        :: "r"(dst_smem), "l"(src_gmem) : "memory")
#define CP_ASYNC_COMMIT() asm volatile("cp.async.commit_group;" ::: "memory")
#define CP_ASYNC_WAIT(n)  asm volatile("cp.async.wait_group %0;" :: "n"(n) : "memory")

__device__ __forceinline__ void stg_cs_v4(float* p, float x, float y, float z, float w) {
    asm volatile("st.global.cs.v4.f32 [%0], {%1,%2,%3,%4};"
                 :: "l"(p), "f"(x), "f"(y), "f"(z), "f"(w) : "memory");
}

// ---------------- Kernel 0: fused pre — transpose (32-v slabs) + prep ----------------
// blocks [0, 2000): transpose 32 columns of W_enc into g_WTb rows (bf16)
// blocks [2000, 2000+8000): prep — one warp per W_dec row
#define TP_BLOCKS   (VTOT / 32)     // 2000
#define PREP_BLOCKS (VTOT / 8)      // 8000

__global__ void __launch_bounds__(256) pre_kernel(const float* __restrict__ Wenc,
                                                  const float* __restrict__ Wdec,
                                                  const float* __restrict__ benc,
                                                  const float* __restrict__ bdec) {
    __shared__ float st[32 * 129];          // 16.5 KB — cheap enough for prep occupancy
    if (blockIdx.x < TP_BLOCKS) {
        int v0 = blockIdx.x * 32;
        int t  = threadIdx.x;
        #pragma unroll
        for (int it = 0; it < 16; ++it) {    // 128 h x 32 v
            int idx = it * 256 + t;
            int v = idx & 31;
            int h = idx >> 5;
            st[v * 129 + h] = Wenc[(size_t)h * VTOT + v0 + v];
        }
        __syncthreads();
        #pragma unroll
        for (int it = 0; it < 4; ++it) {     // 1024 uint2 writes (4 bf16 each)
            int idx = it * 256 + t;
            int h4 = (idx & 31) * 4;
            int v  = idx >> 5;
            __nv_bfloat162 p0 = __floats2bfloat162_rn(st[v * 129 + h4 + 0], st[v * 129 + h4 + 1]);
            __nv_bfloat162 p1 = __floats2bfloat162_rn(st[v * 129 + h4 + 2], st[v * 129 + h4 + 3]);
            uint2 pk;
            pk.x = *reinterpret_cast<uint32_t*>(&p0);
            pk.y = *reinterpret_cast<uint32_t*>(&p1);
            *reinterpret_cast<uint2*>(g_WTb + (size_t)(v0 + v) * HID + h4) = pk;
        }
    } else {
        int gw   = ((blockIdx.x - TP_BLOCKS) * 256 + threadIdx.x) >> 5;
        int lane = threadIdx.x & 31;
        if (gw >= VTOT) return;

        float4 w = *reinterpret_cast<const float4*>(Wdec + (size_t)gw * HID + lane * 4);

        float b0 = benc[lane * 4 + 0], b1 = benc[lane * 4 + 1];
        float b2 = benc[lane * 4 + 2], b3 = benc[lane * 4 + 3];
        float dot = w.x / (1.0f + __expf(-b0)) + w.y / (1.0f + __expf(-b1))
                  + w.z / (1.0f + __expf(-b2)) + w.w / (1.0f + __expf(-b3));

        __nv_bfloat162 p0 = __floats2bfloat162_rn(w.x, w.y);
        __nv_bfloat162 p1 = __floats2bfloat162_rn(w.z, w.w);
        uint2 pk;
        pk.x = *reinterpret_cast<uint32_t*>(&p0);
        pk.y = *reinterpret_cast<uint32_t*>(&p1);
        *reinterpret_cast<uint2*>(g_Wb + (size_t)gw * HID + lane * 4) = pk;

        #pragma unroll
        for (int o = 16; o > 0; o >>= 1) dot += __shfl_xor_sync(0xffffffffu, dot, o);
        if (lane == 0) g_c[gw] = dot + bdec[gw];
    }
}

// ---------------- Kernel 2: encode (bf16 gather rows, fp32 accumulate) ----------------
__global__ void __launch_bounds__(256) encode_kernel(const int* __restrict__ xcat,
                                                     const float* __restrict__ benc,
                                                     float* __restrict__ yout) {
    int wid  = threadIdx.x >> 5;
    int lane = threadIdx.x & 31;
    int b    = blockIdx.x * 8 + wid;

    int gidx = xcat[b * NCOLS + lane] + lane * CATD;

    float a0 = 0.f, a1 = 0.f, a2 = 0.f, a3 = 0.f;
    #pragma unroll
    for (int i = 0; i < NCOLS; ++i) {
        int gi = __shfl_sync(0xffffffffu, gidx, i);
        uint2 pk = *reinterpret_cast<const uint2*>(g_WTb + (size_t)gi * HID + lane * 4);
        __nv_bfloat162 p0 = *reinterpret_cast<__nv_bfloat162*>(&pk.x);
        __nv_bfloat162 p1 = *reinterpret_cast<__nv_bfloat162*>(&pk.y);
        a0 += __bfloat162float(p0.x); a1 += __bfloat162float(p0.y);
        a2 += __bfloat162float(p1.x); a3 += __bfloat162float(p1.y);
    }

    float4 be = *reinterpret_cast<const float4*>(benc + lane * 4);
    float y0 = 1.0f / (1.0f + __expf(-(a0 + be.x)));
    float y1 = 1.0f / (1.0f + __expf(-(a1 + be.y)));
    float y2 = 1.0f / (1.0f + __expf(-(a2 + be.z)));
    float y3 = 1.0f / (1.0f + __expf(-(a3 + be.w)));
    if (yout) {
        float4 yv = {y0, y1, y2, y3};
        *reinterpret_cast<float4*>(yout + (size_t)b * HID + lane * 4) = yv;
    }
    float d0 = y0 - 1.0f / (1.0f + __expf(-be.x));
    float d1 = y1 - 1.0f / (1.0f + __expf(-be.y));
    float d2 = y2 - 1.0f / (1.0f + __expf(-be.z));
    float d3 = y3 - 1.0f / (1.0f + __expf(-be.w));
    __nv_bfloat162 p0 = __floats2bfloat162_rn(d0, d1);
    __nv_bfloat162 p1 = __floats2bfloat162_rn(d2, d3);
    uint2 pk;
    pk.x = *reinterpret_cast<uint32_t*>(&p0);
    pk.y = *reinterpret_cast<uint32_t*>(&p1);
    *reinterpret_cast<uint2*>(g_delta + (size_t)b * HID + lane * 4) = pk;
}

// ---------------- Kernel 3: decode GEMM (R7-validated: 256 thr, 2Mx4N, warp tile 64x32) ------
#define TILE_M 128
#define TILE_N 128
#define NGRP   18
#define NBLKS  (VTOT / TILE_N)           // 500
#define SROWB  272
#define TILE_BYTES (128 * SROWB)         // 34816
#define SM_A_OFF 0
#define SM_B_OFF TILE_BYTES
#define SM_TOTAL (3 * TILE_BYTES)        // 104448

__device__ __forceinline__ void ldmatrix_x4(uint32_t (&r)[4], uint32_t addr) {
    asm volatile("ldmatrix.sync.aligned.m8n8.x4.shared.b16 {%0,%1,%2,%3}, [%4];"
                 : "=r"(r[0]), "=r"(r[1]), "=r"(r[2]), "=r"(r[3]) : "r"(addr));
}
__device__ __forceinline__ void mma_bf16(float (&d)[4], const uint32_t (&a)[4], const uint32_t* b) {
    asm volatile(
        "mma.sync.aligned.m16n8k16.row.col.f32.bf16.bf16.f32 "
        "{%0,%1,%2,%3}, {%4,%5,%6,%7}, {%8,%9}, {%0,%1,%2,%3};"
        : "+f"(d[0]), "+f"(d[1]), "+f"(d[2]), "+f"(d[3])
        : "r"(a[0]), "r"(a[1]), "r"(a[2]), "r"(a[3]), "r"(b[0]), "r"(b[1]));
}

__device__ __forceinline__ void load_B_tile(uint32_t sdst, const char* src, int tid) {
    #pragma unroll
    for (int it = 0; it < 8; ++it) {
        int idx = it * 256 + tid;
        int row = idx >> 4;
        int ch  = (idx & 15) * 16;
        int gg  = row & 15;
        int q   = gg >> 2, r = gg & 3;
        int slot = (r < 2) ? (q * 2 + r) : (8 + q * 2 + (r & 1));
        int prow = (row & ~15) | slot;
        CP_ASYNC_CG16(sdst + prow * SROWB + ch, src + row * 256 + ch);
    }
}

__global__ void __launch_bounds__(256, 2) decode_gemm(float* __restrict__ zout) {
    extern __shared__ char smem[];
    uint32_t sbase = smem_to_u32(smem);
    int tid  = threadIdx.x;
    int wid  = tid >> 5;
    int lane = tid & 31;
    int mblk = blockIdx.x;
    int ygrp = blockIdx.y;

    const char* Asrc = reinterpret_cast<const char*>(g_delta + (size_t)mblk * TILE_M * HID);
    #pragma unroll
    for (int it = 0; it < 8; ++it) {
        int idx = it * 256 + tid;
        int row = idx >> 4;
        int ch  = (idx & 15) * 16;
        CP_ASYNC_CG16(sbase + SM_A_OFF + row * SROWB + ch, Asrc + row * 256 + ch);
    }
    int nb = ygrp;
    load_B_tile(sbase + SM_B_OFF, reinterpret_cast<const char*>(g_Wb + (size_t)nb * TILE_N * HID), tid);
    CP_ASYNC_COMMIT();

    int wm = wid & 1;
    int wn = wid >> 1;
    int j  = lane & 3;
    int colLoc = wn * 32 + j * 4;

    uint32_t aBase = sbase + SM_A_OFF + (uint32_t)(wm * 64 + (lane & 15)) * SROWB + ((lane >> 4) << 4);
    uint32_t bOff  = (uint32_t)(wn * 32 + ((lane >> 4) << 3) + (lane & 7)) * SROWB
                   + (((lane >> 3) & 1) << 4);
    int rowBase = mblk * TILE_M + wm * 64 + (lane >> 2);

    CP_ASYNC_WAIT(0);
    __syncthreads();

    int buf = 0;
    while (true) {
        int nbn = nb + NGRP;
        bool more = (nbn < NBLKS);
        if (more) {
            load_B_tile(sbase + SM_B_OFF + (buf ^ 1) * TILE_BYTES,
                        reinterpret_cast<const char*>(g_Wb + (size_t)nbn * TILE_N * HID), tid);
            CP_ASYNC_COMMIT();
        }

        const float* ctab = g_c + (size_t)nb * TILE_N;
        float4 cv[2];
        cv[0] = *reinterpret_cast<const float4*>(ctab + colLoc);
        cv[1] = *reinterpret_cast<const float4*>(ctab + colLoc + 16);

        float acc[4][4][4];
        #pragma unroll
        for (int i = 0; i < 4; ++i)
            #pragma unroll
            for (int jj = 0; jj < 4; ++jj)
                #pragma unroll
                for (int k = 0; k < 4; ++k) acc[i][jj][k] = 0.0f;

        uint32_t bBase = sbase + SM_B_OFF + (uint32_t)buf * TILE_BYTES + bOff;
        #pragma unroll
        for (int ks = 0; ks < 8; ++ks) {
            uint32_t koff = (uint32_t)ks * 32u;
            uint32_t a[4][4];
            uint32_t b[2][4];
            #pragma unroll
            for (int mf = 0; mf < 4; ++mf)
                ldmatrix_x4(a[mf], aBase + (uint32_t)mf * 16u * SROWB + koff);
            #pragma unroll
            for (int p = 0; p < 2; ++p)
                ldmatrix_x4(b[p], bBase + (uint32_t)p * 16u * SROWB + koff);
            #pragma unroll
            for (int mf = 0; mf < 4; ++mf)
                #pragma unroll
                for (int nf = 0; nf < 4; ++nf)
                    mma_bf16(acc[mf][nf], a[mf], &b[nf >> 1][(nf & 1) * 2]);
        }

        size_t colG = (size_t)nb * TILE_N + colLoc;
        #pragma unroll
        for (int mf = 0; mf < 4; ++mf) {
            float* z0 = zout + (size_t)(rowBase + mf * 16) * VTOT + colG;
            float* z1 = z0 + 8 * VTOT;
            stg_cs_v4(z0,      acc[mf][0][0] + cv[0].x, acc[mf][0][1] + cv[0].y,
                               acc[mf][1][0] + cv[0].z, acc[mf][1][1] + cv[0].w);
            stg_cs_v4(z1,      acc[mf][0][2] + cv[0].x, acc[mf][0][3] + cv[0].y,
                               acc[mf][1][2] + cv[0].z, acc[mf][1][3] + cv[0].w);
            stg_cs_v4(z0 + 16, acc[mf][2][0] + cv[1].x, acc[mf][2][1] + cv[1].y,
                               acc[mf][3][0] + cv[1].z, acc[mf][3][1] + cv[1].w);
            stg_cs_v4(z1 + 16, acc[mf][2][2] + cv[1].x, acc[mf][2][3] + cv[1].y,
                               acc[mf][3][2] + cv[1].z, acc[mf][3][3] + cv[1].w);
        }

        if (!more) break;
        CP_ASYNC_WAIT(0);
        __syncthreads();
        buf ^= 1;
        nb = nbn;
    }
}

// ---------------- Launch ----------------
extern "C" void kernel_launch(void* const* d_in, const int* in_sizes, int n_in,
                              void* d_out, int out_size) {
    const int*   xcat = (const int*)d_in[0];
    const float* Wenc = (const float*)d_in[1];
    const float* benc = (const float*)d_in[2];
    const float* Wdec = (const float*)d_in[3];
    const float* bdec = (const float*)d_in[4];

    float* out = (float*)d_out;
    long long ztotal = (long long)BATCH * VTOT;
    long long zoff   = (long long)out_size - ztotal;
    if (zoff < 0) zoff = 0;
    float* zout = out + zoff;
    float* yout = (zoff >= (long long)BATCH * HID) ? out : nullptr;

    cudaFuncSetAttribute(decode_gemm, cudaFuncAttributeMaxDynamicSharedMemorySize, SM_TOTAL);

    pre_kernel<<<TP_BLOCKS + PREP_BLOCKS, 256>>>(Wenc, Wdec, benc, bdec);
    encode_kernel<<<BATCH / 8, 256>>>(xcat, benc, yout);
    decode_gemm<<<dim3(BATCH / TILE_M, NGRP), 256, SM_TOTAL>>>(zout);
}

// round 10
// speedup vs baseline: 1.5043x; 1.1111x over previous
#include <cuda_runtime.h>
#include <cuda_bf16.h>
#include <cstdint>

// ---------------- Problem constants ----------------
#define BATCH   2048
#define NCOLS   32
#define CATD    2000
#define HID     128
#define VTOT    64000

// ---------------- Device scratch (no allocs allowed) ----------------
__device__ __align__(16) __nv_bfloat16 g_Wb[VTOT * HID];      // 16 MB  bf16 W_dec
__device__ __align__(16) float         g_c[VTOT];             // 256 KB c[v]
__device__ __align__(16) __nv_bfloat16 g_delta[BATCH * HID];  // 512 KB bf16 (y - ybar)
__device__ __align__(16) __nv_bfloat16 g_WTb[VTOT * HID];     // 16 MB  W_enc^T [v][h] bf16

__device__ __forceinline__ uint32_t smem_to_u32(const void* p) {
    uint32_t a;
    asm("{ .reg .u64 t; cvta.to.shared.u64 t, %1; cvt.u32.u64 %0, t; }" : "=r"(a) : "l"(p));
    return a;
}

#define CP_ASYNC_CG16(dst_smem, src_gmem) \
    asm volatile("cp.async.cg.shared.global [%0], [%1], 16;" \
        :: "r"(dst_smem), "l"(src_gmem) : "memory")
#define CP_ASYNC_COMMIT() asm volatile("cp.async.commit_group;" ::: "memory")
#define CP_ASYNC_WAIT(n)  asm volatile("cp.async.wait_group %0;" :: "n"(n) : "memory")

__device__ __forceinline__ void stg_cs_v4(float* p, float x, float y, float z, float w) {
    asm volatile("st.global.cs.v4.f32 [%0], {%1,%2,%3,%4};"
                 :: "l"(p), "f"(x), "f"(y), "f"(z), "f"(w) : "memory");
}

// ---------------- Kernel 0: fused pre — transpose (32-v slabs) + prep ----------------
#define TP_BLOCKS   (VTOT / 32)     // 2000
#define PREP_BLOCKS (VTOT / 8)      // 8000

__global__ void __launch_bounds__(256) pre_kernel(const float* __restrict__ Wenc,
                                                  const float* __restrict__ Wdec,
                                                  const float* __restrict__ benc,
                                                  const float* __restrict__ bdec) {
    __shared__ float st[32 * 129];
    if (blockIdx.x < TP_BLOCKS) {
        int v0 = blockIdx.x * 32;
        int t  = threadIdx.x;
        #pragma unroll
        for (int it = 0; it < 16; ++it) {
            int idx = it * 256 + t;
            int v = idx & 31;
            int h = idx >> 5;
            st[v * 129 + h] = Wenc[(size_t)h * VTOT + v0 + v];
        }
        __syncthreads();
        #pragma unroll
        for (int it = 0; it < 4; ++it) {
            int idx = it * 256 + t;
            int h4 = (idx & 31) * 4;
            int v  = idx >> 5;
            __nv_bfloat162 p0 = __floats2bfloat162_rn(st[v * 129 + h4 + 0], st[v * 129 + h4 + 1]);
            __nv_bfloat162 p1 = __floats2bfloat162_rn(st[v * 129 + h4 + 2], st[v * 129 + h4 + 3]);
            uint2 pk;
            pk.x = *reinterpret_cast<uint32_t*>(&p0);
            pk.y = *reinterpret_cast<uint32_t*>(&p1);
            *reinterpret_cast<uint2*>(g_WTb + (size_t)(v0 + v) * HID + h4) = pk;
        }
    } else {
        int gw   = ((blockIdx.x - TP_BLOCKS) * 256 + threadIdx.x) >> 5;
        int lane = threadIdx.x & 31;
        if (gw >= VTOT) return;

        float4 w = *reinterpret_cast<const float4*>(Wdec + (size_t)gw * HID + lane * 4);

        float b0 = benc[lane * 4 + 0], b1 = benc[lane * 4 + 1];
        float b2 = benc[lane * 4 + 2], b3 = benc[lane * 4 + 3];
        float dot = w.x / (1.0f + __expf(-b0)) + w.y / (1.0f + __expf(-b1))
                  + w.z / (1.0f + __expf(-b2)) + w.w / (1.0f + __expf(-b3));

        __nv_bfloat162 p0 = __floats2bfloat162_rn(w.x, w.y);
        __nv_bfloat162 p1 = __floats2bfloat162_rn(w.z, w.w);
        uint2 pk;
        pk.x = *reinterpret_cast<uint32_t*>(&p0);
        pk.y = *reinterpret_cast<uint32_t*>(&p1);
        *reinterpret_cast<uint2*>(g_Wb + (size_t)gw * HID + lane * 4) = pk;

        #pragma unroll
        for (int o = 16; o > 0; o >>= 1) dot += __shfl_xor_sync(0xffffffffu, dot, o);
        if (lane == 0) g_c[gw] = dot + bdec[gw];
    }
}

// ---------------- Kernel 2: encode (bf16 gather rows, fp32 accumulate) ----------------
__global__ void __launch_bounds__(256) encode_kernel(const int* __restrict__ xcat,
                                                     const float* __restrict__ benc,
                                                     float* __restrict__ yout) {
    int wid  = threadIdx.x >> 5;
    int lane = threadIdx.x & 31;
    int b    = blockIdx.x * 8 + wid;

    int gidx = xcat[b * NCOLS + lane] + lane * CATD;

    float a0 = 0.f, a1 = 0.f, a2 = 0.f, a3 = 0.f;
    #pragma unroll
    for (int i = 0; i < NCOLS; ++i) {
        int gi = __shfl_sync(0xffffffffu, gidx, i);
        uint2 pk = *reinterpret_cast<const uint2*>(g_WTb + (size_t)gi * HID + lane * 4);
        __nv_bfloat162 p0 = *reinterpret_cast<__nv_bfloat162*>(&pk.x);
        __nv_bfloat162 p1 = *reinterpret_cast<__nv_bfloat162*>(&pk.y);
        a0 += __bfloat162float(p0.x); a1 += __bfloat162float(p0.y);
        a2 += __bfloat162float(p1.x); a3 += __bfloat162float(p1.y);
    }

    float4 be = *reinterpret_cast<const float4*>(benc + lane * 4);
    float y0 = 1.0f / (1.0f + __expf(-(a0 + be.x)));
    float y1 = 1.0f / (1.0f + __expf(-(a1 + be.y)));
    float y2 = 1.0f / (1.0f + __expf(-(a2 + be.z)));
    float y3 = 1.0f / (1.0f + __expf(-(a3 + be.w)));
    if (yout) {
        float4 yv = {y0, y1, y2, y3};
        *reinterpret_cast<float4*>(yout + (size_t)b * HID + lane * 4) = yv;
    }
    float d0 = y0 - 1.0f / (1.0f + __expf(-be.x));
    float d1 = y1 - 1.0f / (1.0f + __expf(-be.y));
    float d2 = y2 - 1.0f / (1.0f + __expf(-be.z));
    float d3 = y3 - 1.0f / (1.0f + __expf(-be.w));
    __nv_bfloat162 p0 = __floats2bfloat162_rn(d0, d1);
    __nv_bfloat162 p1 = __floats2bfloat162_rn(d2, d3);
    uint2 pk;
    pk.x = *reinterpret_cast<uint32_t*>(&p0);
    pk.y = *reinterpret_cast<uint32_t*>(&p1);
    *reinterpret_cast<uint2*>(g_delta + (size_t)b * HID + lane * 4) = pk;
}

// ---------------- Kernel 3: decode GEMM — 256 thr, 2Mx4N, B frags hoisted, mf-outer loop -----
#define TILE_M 128
#define TILE_N 128
#define NGRP   18
#define NBLKS  (VTOT / TILE_N)           // 500
#define SROWB  272
#define TILE_BYTES (128 * SROWB)         // 34816
#define SM_A_OFF 0
#define SM_B_OFF TILE_BYTES
#define SM_TOTAL (3 * TILE_BYTES)        // 104448

__device__ __forceinline__ void ldmatrix_x4(uint32_t (&r)[4], uint32_t addr) {
    asm volatile("ldmatrix.sync.aligned.m8n8.x4.shared.b16 {%0,%1,%2,%3}, [%4];"
                 : "=r"(r[0]), "=r"(r[1]), "=r"(r[2]), "=r"(r[3]) : "r"(addr));
}
__device__ __forceinline__ void mma_bf16(float (&d)[4], const uint32_t (&a)[4], const uint32_t* b) {
    asm volatile(
        "mma.sync.aligned.m16n8k16.row.col.f32.bf16.bf16.f32 "
        "{%0,%1,%2,%3}, {%4,%5,%6,%7}, {%8,%9}, {%0,%1,%2,%3};"
        : "+f"(d[0]), "+f"(d[1]), "+f"(d[2]), "+f"(d[3])
        : "r"(a[0]), "r"(a[1]), "r"(a[2]), "r"(a[3]), "r"(b[0]), "r"(b[1]));
}

__device__ __forceinline__ void load_B_tile(uint32_t sdst, const char* src, int tid) {
    #pragma unroll
    for (int it = 0; it < 8; ++it) {
        int idx = it * 256 + tid;
        int row = idx >> 4;
        int ch  = (idx & 15) * 16;
        int gg  = row & 15;
        int q   = gg >> 2, r = gg & 3;
        int slot = (r < 2) ? (q * 2 + r) : (8 + q * 2 + (r & 1));
        int prow = (row & ~15) | slot;
        CP_ASYNC_CG16(sdst + prow * SROWB + ch, src + row * 256 + ch);
    }
}

__global__ void __launch_bounds__(256, 2) decode_gemm(float* __restrict__ zout) {
    extern __shared__ char smem[];
    uint32_t sbase = smem_to_u32(smem);
    int tid  = threadIdx.x;
    int wid  = tid >> 5;
    int lane = tid & 31;
    int mblk = blockIdx.x;
    int ygrp = blockIdx.y;

    const char* Asrc = reinterpret_cast<const char*>(g_delta + (size_t)mblk * TILE_M * HID);
    #pragma unroll
    for (int it = 0; it < 8; ++it) {
        int idx = it * 256 + tid;
        int row = idx >> 4;
        int ch  = (idx & 15) * 16;
        CP_ASYNC_CG16(sbase + SM_A_OFF + row * SROWB + ch, Asrc + row * 256 + ch);
    }
    int nb = ygrp;
    load_B_tile(sbase + SM_B_OFF, reinterpret_cast<const char*>(g_Wb + (size_t)nb * TILE_N * HID), tid);
    CP_ASYNC_COMMIT();

    int wm = wid & 1;
    int wn = wid >> 1;
    int j  = lane & 3;
    int colLoc = wn * 32 + j * 4;

    uint32_t aBase = sbase + SM_A_OFF + (uint32_t)(wm * 64 + (lane & 15)) * SROWB + ((lane >> 4) << 4);
    uint32_t bOff  = (uint32_t)(wn * 32 + ((lane >> 4) << 3) + (lane & 7)) * SROWB
                   + (((lane >> 3) & 1) << 4);
    int rowBase = mblk * TILE_M + wm * 64 + (lane >> 2);

    CP_ASYNC_WAIT(0);
    __syncthreads();

    int buf = 0;
    while (true) {
        int nbn = nb + NGRP;
        bool more = (nbn < NBLKS);
        if (more) {
            load_B_tile(sbase + SM_B_OFF + (buf ^ 1) * TILE_BYTES,
                        reinterpret_cast<const char*>(g_Wb + (size_t)nbn * TILE_N * HID), tid);
            CP_ASYNC_COMMIT();
        }

        const float* ctab = g_c + (size_t)nb * TILE_N;
        float4 cv[2];
        cv[0] = *reinterpret_cast<const float4*>(ctab + colLoc);
        cv[1] = *reinterpret_cast<const float4*>(ctab + colLoc + 16);

        // ---- hoist ALL B fragments for this tile (16 LDSM.x4) ----
        uint32_t bBase = sbase + SM_B_OFF + (uint32_t)buf * TILE_BYTES + bOff;
        uint32_t ball[8][2][4];
        #pragma unroll
        for (int ks = 0; ks < 8; ++ks)
            #pragma unroll
            for (int p = 0; p < 2; ++p)
                ldmatrix_x4(ball[ks][p], bBase + (uint32_t)p * 16u * SROWB + (uint32_t)ks * 32u);

        size_t colG = (size_t)nb * TILE_N + colLoc;

        // ---- mf-outer: compute one 16-row strip, store it, move on ----
        #pragma unroll
        for (int mf = 0; mf < 4; ++mf) {
            float acc[4][4];
            #pragma unroll
            for (int jj = 0; jj < 4; ++jj)
                #pragma unroll
                for (int k = 0; k < 4; ++k) acc[jj][k] = 0.0f;

            #pragma unroll
            for (int ks = 0; ks < 8; ++ks) {
                uint32_t a[4];
                ldmatrix_x4(a, aBase + (uint32_t)mf * 16u * SROWB + (uint32_t)ks * 32u);
                #pragma unroll
                for (int nf = 0; nf < 4; ++nf)
                    mma_bf16(acc[nf], a, &ball[ks][nf >> 1][(nf & 1) * 2]);
            }

            float* z0 = zout + (size_t)(rowBase + mf * 16) * VTOT + colG;
            float* z1 = z0 + 8 * VTOT;
            stg_cs_v4(z0,      acc[0][0] + cv[0].x, acc[0][1] + cv[0].y,
                               acc[1][0] + cv[0].z, acc[1][1] + cv[0].w);
            stg_cs_v4(z1,      acc[0][2] + cv[0].x, acc[0][3] + cv[0].y,
                               acc[1][2] + cv[0].z, acc[1][3] + cv[0].w);
            stg_cs_v4(z0 + 16, acc[2][0] + cv[1].x, acc[2][1] + cv[1].y,
                               acc[3][0] + cv[1].z, acc[3][1] + cv[1].w);
            stg_cs_v4(z1 + 16, acc[2][2] + cv[1].x, acc[2][3] + cv[1].y,
                               acc[3][2] + cv[1].z, acc[3][3] + cv[1].w);
        }

        if (!more) break;
        CP_ASYNC_WAIT(0);
        __syncthreads();
        buf ^= 1;
        nb = nbn;
    }
}

// ---------------- Launch ----------------
extern "C" void kernel_launch(void* const* d_in, const int* in_sizes, int n_in,
                              void* d_out, int out_size) {
    const int*   xcat = (const int*)d_in[0];
    const float* Wenc = (const float*)d_in[1];
    const float* benc = (const float*)d_in[2];
    const float* Wdec = (const float*)d_in[3];
    const float* bdec = (const float*)d_in[4];

    float* out = (float*)d_out;
    long long ztotal = (long long)BATCH * VTOT;
    long long zoff   = (long long)out_size - ztotal;
    if (zoff < 0) zoff = 0;
    float* zout = out + zoff;
    float* yout = (zoff >= (long long)BATCH * HID) ? out : nullptr;

    cudaFuncSetAttribute(decode_gemm, cudaFuncAttributeMaxDynamicSharedMemorySize, SM_TOTAL);

    pre_kernel<<<TP_BLOCKS + PREP_BLOCKS, 256>>>(Wenc, Wdec, benc, bdec);
    encode_kernel<<<BATCH / 8, 256>>>(xcat, benc, yout);
    decode_gemm<<<dim3(BATCH / TILE_M, NGRP), 256, SM_TOTAL>>>(zout);
}

// round 11
// speedup vs baseline: 1.5648x; 1.0402x over previous
#include <cuda_runtime.h>
#include <cuda_bf16.h>
#include <cstdint>

// ---------------- Problem constants ----------------
#define BATCH   2048
#define NCOLS   32
#define CATD    2000
#define HID     128
#define VTOT    64000

// ---------------- Device scratch (no allocs allowed) ----------------
__device__ __align__(16) __nv_bfloat16 g_Wb[VTOT * HID];      // 16 MB  bf16 W_dec
__device__ __align__(16) float         g_c[VTOT];             // 256 KB c[v]
__device__ __align__(16) __nv_bfloat16 g_delta[BATCH * HID];  // 512 KB bf16 (y - ybar)
__device__ __align__(16) __nv_bfloat16 g_WTb[VTOT * HID];     // 16 MB  W_enc^T [v][h] bf16

__device__ __forceinline__ uint32_t smem_to_u32(const void* p) {
    uint32_t a;
    asm("{ .reg .u64 t; cvta.to.shared.u64 t, %1; cvt.u32.u64 %0, t; }" : "=r"(a) : "l"(p));
    return a;
}

#define CP_ASYNC_CG16(dst_smem, src_gmem) \
    asm volatile("cp.async.cg.shared.global [%0], [%1], 16;" \
        :: "r"(dst_smem), "l"(src_gmem) : "memory")
#define CP_ASYNC_COMMIT() asm volatile("cp.async.commit_group;" ::: "memory")
#define CP_ASYNC_WAIT(n)  asm volatile("cp.async.wait_group %0;" :: "n"(n) : "memory")

__device__ __forceinline__ void stg_cs_v4(float* p, float x, float y, float z, float w) {
    asm volatile("st.global.cs.v4.f32 [%0], {%1,%2,%3,%4};"
                 :: "l"(p), "f"(x), "f"(y), "f"(z), "f"(w) : "memory");
}

// ---------------- Kernel 0: fused pre — transpose (32-v slabs) + prep ----------------
#define TP_BLOCKS   (VTOT / 32)     // 2000
#define PREP_BLOCKS (VTOT / 8)      // 8000

__global__ void __launch_bounds__(256) pre_kernel(const float* __restrict__ Wenc,
                                                  const float* __restrict__ Wdec,
                                                  const float* __restrict__ benc,
                                                  const float* __restrict__ bdec) {
    __shared__ float st[32 * 129];
    if (blockIdx.x < TP_BLOCKS) {
        int v0 = blockIdx.x * 32;
        int t  = threadIdx.x;
        #pragma unroll
        for (int it = 0; it < 16; ++it) {
            int idx = it * 256 + t;
            int v = idx & 31;
            int h = idx >> 5;
            st[v * 129 + h] = Wenc[(size_t)h * VTOT + v0 + v];
        }
        __syncthreads();
        #pragma unroll
        for (int it = 0; it < 4; ++it) {
            int idx = it * 256 + t;
            int h4 = (idx & 31) * 4;
            int v  = idx >> 5;
            __nv_bfloat162 p0 = __floats2bfloat162_rn(st[v * 129 + h4 + 0], st[v * 129 + h4 + 1]);
            __nv_bfloat162 p1 = __floats2bfloat162_rn(st[v * 129 + h4 + 2], st[v * 129 + h4 + 3]);
            uint2 pk;
            pk.x = *reinterpret_cast<uint32_t*>(&p0);
            pk.y = *reinterpret_cast<uint32_t*>(&p1);
            *reinterpret_cast<uint2*>(g_WTb + (size_t)(v0 + v) * HID + h4) = pk;
        }
    } else {
        int gw   = ((blockIdx.x - TP_BLOCKS) * 256 + threadIdx.x) >> 5;
        int lane = threadIdx.x & 31;
        if (gw >= VTOT) return;

        float4 w = *reinterpret_cast<const float4*>(Wdec + (size_t)gw * HID + lane * 4);

        float b0 = benc[lane * 4 + 0], b1 = benc[lane * 4 + 1];
        float b2 = benc[lane * 4 + 2], b3 = benc[lane * 4 + 3];
        float dot = w.x / (1.0f + __expf(-b0)) + w.y / (1.0f + __expf(-b1))
                  + w.z / (1.0f + __expf(-b2)) + w.w / (1.0f + __expf(-b3));

        __nv_bfloat162 p0 = __floats2bfloat162_rn(w.x, w.y);
        __nv_bfloat162 p1 = __floats2bfloat162_rn(w.z, w.w);
        uint2 pk;
        pk.x = *reinterpret_cast<uint32_t*>(&p0);
        pk.y = *reinterpret_cast<uint32_t*>(&p1);
        *reinterpret_cast<uint2*>(g_Wb + (size_t)gw * HID + lane * 4) = pk;

        #pragma unroll
        for (int o = 16; o > 0; o >>= 1) dot += __shfl_xor_sync(0xffffffffu, dot, o);
        if (lane == 0) g_c[gw] = dot + bdec[gw];
    }
}

// ---------------- Kernel 2: encode (bf16 gather rows, fp32 accumulate) ----------------
__global__ void __launch_bounds__(256) encode_kernel(const int* __restrict__ xcat,
                                                     const float* __restrict__ benc,
                                                     float* __restrict__ yout) {
    int wid  = threadIdx.x >> 5;
    int lane = threadIdx.x & 31;
    int b    = blockIdx.x * 8 + wid;

    int gidx = xcat[b * NCOLS + lane] + lane * CATD;

    float a0 = 0.f, a1 = 0.f, a2 = 0.f, a3 = 0.f;
    #pragma unroll
    for (int i = 0; i < NCOLS; ++i) {
        int gi = __shfl_sync(0xffffffffu, gidx, i);
        uint2 pk = *reinterpret_cast<const uint2*>(g_WTb + (size_t)gi * HID + lane * 4);
        __nv_bfloat162 p0 = *reinterpret_cast<__nv_bfloat162*>(&pk.x);
        __nv_bfloat162 p1 = *reinterpret_cast<__nv_bfloat162*>(&pk.y);
        a0 += __bfloat162float(p0.x); a1 += __bfloat162float(p0.y);
        a2 += __bfloat162float(p1.x); a3 += __bfloat162float(p1.y);
    }

    float4 be = *reinterpret_cast<const float4*>(benc + lane * 4);
    float y0 = 1.0f / (1.0f + __expf(-(a0 + be.x)));
    float y1 = 1.0f / (1.0f + __expf(-(a1 + be.y)));
    float y2 = 1.0f / (1.0f + __expf(-(a2 + be.z)));
    float y3 = 1.0f / (1.0f + __expf(-(a3 + be.w)));
    if (yout) {
        float4 yv = {y0, y1, y2, y3};
        *reinterpret_cast<float4*>(yout + (size_t)b * HID + lane * 4) = yv;
    }
    float d0 = y0 - 1.0f / (1.0f + __expf(-be.x));
    float d1 = y1 - 1.0f / (1.0f + __expf(-be.y));
    float d2 = y2 - 1.0f / (1.0f + __expf(-be.z));
    float d3 = y3 - 1.0f / (1.0f + __expf(-be.w));
    __nv_bfloat162 p0 = __floats2bfloat162_rn(d0, d1);
    __nv_bfloat162 p1 = __floats2bfloat162_rn(d2, d3);
    uint2 pk;
    pk.x = *reinterpret_cast<uint32_t*>(&p0);
    pk.y = *reinterpret_cast<uint32_t*>(&p1);
    *reinterpret_cast<uint2*>(g_delta + (size_t)b * HID + lane * 4) = pk;
}

// ---------------- Kernel 3: decode GEMM — B-RESIDENT, A-streamed ----------------
// Grid (2, 500): CTA = (mhalf, nblk). B tile loaded once, fragments hoisted to
// registers for CTA lifetime (16 LDSM). A tiles (8 per CTA) stream via cp.async
// double buffer; 32 A-LDSM per tile. mf-outer compute with interleaved STG.128.
// B rows permuted within 16-row groups (validated R5/R10 mapping).

#define TILE_M 128
#define TILE_N 128
#define MTILES 16                        // BATCH / TILE_M
#define MHALF  8                         // tiles per CTA
#define NBLKS  (VTOT / TILE_N)           // 500
#define SROWB  272
#define TILE_BYTES (128 * SROWB)         // 34816
#define SM_TOTAL (3 * TILE_BYTES)        // 104448 (B + 2x A)

__device__ __forceinline__ void ldmatrix_x4(uint32_t (&r)[4], uint32_t addr) {
    asm volatile("ldmatrix.sync.aligned.m8n8.x4.shared.b16 {%0,%1,%2,%3}, [%4];"
                 : "=r"(r[0]), "=r"(r[1]), "=r"(r[2]), "=r"(r[3]) : "r"(addr));
}
__device__ __forceinline__ void mma_bf16(float (&d)[4], const uint32_t (&a)[4], const uint32_t* b) {
    asm volatile(
        "mma.sync.aligned.m16n8k16.row.col.f32.bf16.bf16.f32 "
        "{%0,%1,%2,%3}, {%4,%5,%6,%7}, {%8,%9}, {%0,%1,%2,%3};"
        : "+f"(d[0]), "+f"(d[1]), "+f"(d[2]), "+f"(d[3])
        : "r"(a[0]), "r"(a[1]), "r"(a[2]), "r"(a[3]), "r"(b[0]), "r"(b[1]));
}

// Permuted B loader (cols -> STG.128-friendly slots)
__device__ __forceinline__ void load_B_tile(uint32_t sdst, const char* src, int tid) {
    #pragma unroll
    for (int it = 0; it < 8; ++it) {
        int idx = it * 256 + tid;
        int row = idx >> 4;
        int ch  = (idx & 15) * 16;
        int gg  = row & 15;
        int q   = gg >> 2, r = gg & 3;
        int slot = (r < 2) ? (q * 2 + r) : (8 + q * 2 + (r & 1));
        int prow = (row & ~15) | slot;
        CP_ASYNC_CG16(sdst + prow * SROWB + ch, src + row * 256 + ch);
    }
}
// Plain A loader
__device__ __forceinline__ void load_A_tile(uint32_t sdst, const char* src, int tid) {
    #pragma unroll
    for (int it = 0; it < 8; ++it) {
        int idx = it * 256 + tid;
        int row = idx >> 4;
        int ch  = (idx & 15) * 16;
        CP_ASYNC_CG16(sdst + row * SROWB + ch, src + row * 256 + ch);
    }
}

__global__ void __launch_bounds__(256, 2) decode_gemm(float* __restrict__ zout) {
    extern __shared__ char smem[];
    uint32_t sbase = smem_to_u32(smem);
    int tid   = threadIdx.x;
    int wid   = tid >> 5;
    int lane  = tid & 31;
    int mhalf = blockIdx.x;   // 0..1
    int nb    = blockIdx.y;   // 0..499

    // ---- B tile once + first A tile (one commit group) ----
    load_B_tile(sbase, reinterpret_cast<const char*>(g_Wb + (size_t)nb * TILE_N * HID), tid);
    int mt0 = mhalf * MHALF;
    load_A_tile(sbase + TILE_BYTES,
                reinterpret_cast<const char*>(g_delta + (size_t)mt0 * TILE_M * HID), tid);
    CP_ASYNC_COMMIT();

    int wm = wid & 1;
    int wn = wid >> 1;
    int j  = lane & 3;
    int colLoc = wn * 32 + j * 4;

    uint32_t aOff = (uint32_t)(wm * 64 + (lane & 15)) * SROWB + ((lane >> 4) << 4);
    uint32_t bOff = (uint32_t)(wn * 32 + ((lane >> 4) << 3) + (lane & 7)) * SROWB
                  + (((lane >> 3) & 1) << 4);

    // epilogue constants (CTA-invariant)
    const float* ctab = g_c + (size_t)nb * TILE_N;
    float4 cv[2];
    cv[0] = *reinterpret_cast<const float4*>(ctab + colLoc);
    cv[1] = *reinterpret_cast<const float4*>(ctab + colLoc + 16);
    size_t colG = (size_t)nb * TILE_N + colLoc;

    CP_ASYNC_WAIT(0);
    __syncthreads();

    // ---- hoist ALL B fragments for CTA lifetime (16 LDSM.x4) ----
    uint32_t ball[8][2][4];
    #pragma unroll
    for (int ks = 0; ks < 8; ++ks)
        #pragma unroll
        for (int p = 0; p < 2; ++p)
            ldmatrix_x4(ball[ks][p], sbase + bOff + (uint32_t)p * 16u * SROWB + (uint32_t)ks * 32u);

    int buf = 0;   // A buffer: offset TILE_BYTES * (1 + buf)
    #pragma unroll 1
    for (int mt = 0; mt < MHALF; ++mt) {
        if (mt < MHALF - 1) {
            load_A_tile(sbase + TILE_BYTES * (1 + (buf ^ 1)),
                        reinterpret_cast<const char*>(g_delta + (size_t)(mt0 + mt + 1) * TILE_M * HID),
                        tid);
            CP_ASYNC_COMMIT();
        }

        uint32_t aBase = sbase + TILE_BYTES * (1 + buf) + aOff;
        int rowBase = (mt0 + mt) * TILE_M + wm * 64 + (lane >> 2);

        #pragma unroll
        for (int mf = 0; mf < 4; ++mf) {
            float acc[4][4];
            #pragma unroll
            for (int jj = 0; jj < 4; ++jj)
                #pragma unroll
                for (int k = 0; k < 4; ++k) acc[jj][k] = 0.0f;

            #pragma unroll
            for (int ks = 0; ks < 8; ++ks) {
                uint32_t a[4];
                ldmatrix_x4(a, aBase + (uint32_t)mf * 16u * SROWB + (uint32_t)ks * 32u);
                #pragma unroll
                for (int nf = 0; nf < 4; ++nf)
                    mma_bf16(acc[nf], a, &ball[ks][nf >> 1][(nf & 1) * 2]);
            }

            float* z0 = zout + (size_t)(rowBase + mf * 16) * VTOT + colG;
            float* z1 = z0 + 8 * VTOT;
            stg_cs_v4(z0,      acc[0][0] + cv[0].x, acc[0][1] + cv[0].y,
                               acc[1][0] + cv[0].z, acc[1][1] + cv[0].w);
            stg_cs_v4(z1,      acc[0][2] + cv[0].x, acc[0][3] + cv[0].y,
                               acc[1][2] + cv[0].z, acc[1][3] + cv[0].w);
            stg_cs_v4(z0 + 16, acc[2][0] + cv[1].x, acc[2][1] + cv[1].y,
                               acc[3][0] + cv[1].z, acc[3][1] + cv[1].w);
            stg_cs_v4(z1 + 16, acc[2][2] + cv[1].x, acc[2][3] + cv[1].y,
                               acc[3][2] + cv[1].z, acc[3][3] + cv[1].w);
        }

        if (mt == MHALF - 1) break;
        CP_ASYNC_WAIT(0);
        __syncthreads();
        buf ^= 1;
    }
}

// ---------------- Launch ----------------
extern "C" void kernel_launch(void* const* d_in, const int* in_sizes, int n_in,
                              void* d_out, int out_size) {
    const int*   xcat = (const int*)d_in[0];
    const float* Wenc = (const float*)d_in[1];
    const float* benc = (const float*)d_in[2];
    const float* Wdec = (const float*)d_in[3];
    const float* bdec = (const float*)d_in[4];

    float* out = (float*)d_out;
    long long ztotal = (long long)BATCH * VTOT;
    long long zoff   = (long long)out_size - ztotal;
    if (zoff < 0) zoff = 0;
    float* zout = out + zoff;
    float* yout = (zoff >= (long long)BATCH * HID) ? out : nullptr;

    cudaFuncSetAttribute(decode_gemm, cudaFuncAttributeMaxDynamicSharedMemorySize, SM_TOTAL);

    pre_kernel<<<TP_BLOCKS + PREP_BLOCKS, 256>>>(Wenc, Wdec, benc, bdec);
    encode_kernel<<<BATCH / 8, 256>>>(xcat, benc, yout);
    decode_gemm<<<dim3(2, NBLKS), 256, SM_TOTAL>>>(zout);
}